// round 15
// baseline (speedup 1.0000x reference)
#include <cuda_runtime.h>
#include <cuda_fp16.h>
#include <math.h>
#include <stdint.h>

// ---------------- problem dims -------------------------------------------
#define Bc 4
#define Tc 4096
#define Dc 1024
#define Hc 1024
#define BHc (Bc * Hc)
#define NCHUNK 128
#define CLEN (Tc / NCHUNK)       // 32

// ---------------- GEMM geometry ------------------------------------------
// fp16 single-pass GEMM, mbarrier pipeline, fused log-space epilogue AND
// fused per-chunk scan summaries (CTA owns 8 complete 32-t chunks).
// CTA tile 256(M) x 128(N), 512 threads (16 warps), warp tile 64M x 32N,
// 1 CTA/SM, 4 stages. Halves W re-read traffic vs BM=128 (1.5GB -> 1.0GB).
#define BM 256
#define BN 128
#define NTILES 16                // K = 1024
#define STAGES 4
#define A_BYTES (BM * 128)       // 32768
#define B_BYTES (BN * 128)       // 16384
#define STAGE_BYTES (A_BYTES + B_BYTES)   // 49152
#define SM_BAR (STAGES * STAGE_BYTES)     // 196608
#define SMEM_TOTAL (SM_BAR + 96)          // 196704 (1 CTA/SM)
// epilogue transpose tile aliases the pipeline buffers: [256][67] float2
#define TP_STRIDE 67                      // float2 units; 256*67*8 = 137216 B

// ---------------- scratch globals ----------------------------------------
__device__ __align__(1024) __half gx[(size_t)Bc * Tc * Dc];    // fp16 x
__device__ __align__(1024) __half gw[2048 * 1024];             // fp16 [Wz;Wh]
__device__ float2 g_lcv[(size_t)Bc * Tc * Hc];                 // (lc, lv)
__device__ float g_A[NCHUNK * BHc];
__device__ float g_R[NCHUNK * BHc];
__device__ float g_hin[NCHUNK * BHc];

// ---------------- PTX helpers --------------------------------------------
__device__ __forceinline__ uint32_t smem_u32(const void* p) {
    uint32_t a;
    asm("{ .reg .u64 t; cvta.to.shared.u64 t, %1; cvt.u32.u64 %0, t; }"
        : "=r"(a) : "l"(p));
    return a;
}
__device__ __forceinline__ void cp_async16(uint32_t dst, const void* src) {
    asm volatile("cp.async.cg.shared.global [%0], [%1], 16;"
                 :: "r"(dst), "l"(src) : "memory");
}
__device__ __forceinline__ void mbar_init(uint32_t a, uint32_t cnt) {
    asm volatile("mbarrier.init.shared.b64 [%0], %1;" :: "r"(a), "r"(cnt) : "memory");
}
__device__ __forceinline__ void mbar_arrive(uint32_t a) {
    asm volatile("{ .reg .b64 t; mbarrier.arrive.shared.b64 t, [%0]; }"
                 :: "r"(a) : "memory");
}
__device__ __forceinline__ void cp_async_mbar_arrive(uint32_t a) {
    asm volatile("cp.async.mbarrier.arrive.noinc.shared.b64 [%0];"
                 :: "r"(a) : "memory");
}
__device__ __forceinline__ void mbar_wait(uint32_t a, uint32_t parity) {
    asm volatile(
        "{\n\t.reg .pred P;\n"
        "W_%=:\n\t"
        "mbarrier.try_wait.parity.shared.b64 P, [%0], %1;\n\t"
        "@P bra.uni D_%=;\n\t"
        "bra.uni W_%=;\n\t"
        "D_%=:\n\t}" :: "r"(a), "r"(parity) : "memory");
}

#define LDSM_X4(r0, r1, r2, r3, addr) \
    asm volatile("ldmatrix.sync.aligned.m8n8.x4.shared.b16 {%0,%1,%2,%3}, [%4];" \
                 : "=r"(r0), "=r"(r1), "=r"(r2), "=r"(r3) : "r"(addr))

__device__ __forceinline__ void mma_f16(float* c, const uint32_t* a,
                                        const uint32_t* b) {
    asm volatile(
        "mma.sync.aligned.m16n8k16.row.col.f32.f16.f16.f32 "
        "{%0,%1,%2,%3}, {%4,%5,%6,%7}, {%8,%9}, {%0,%1,%2,%3};"
        : "+f"(c[0]), "+f"(c[1]), "+f"(c[2]), "+f"(c[3])
        : "r"(a[0]), "r"(a[1]), "r"(a[2]), "r"(a[3]), "r"(b[0]), "r"(b[1]));
}

// ---------------- math helpers -------------------------------------------
__device__ __forceinline__ float softplus_f(float u) {
    return fmaxf(u, 0.f) + __logf(1.f + __expf(-fabsf(u)));
}
__device__ __forceinline__ float log_g_f(float v) {
    return (v >= 0.f) ? __logf(v + 0.5f) : -softplus_f(-v);
}
__device__ __forceinline__ float logaddexp_f(float a, float b) {
    float m = fmaxf(a, b);
    if (m == -INFINITY) return -INFINITY;
    return m + __logf(1.f + __expf(-fabsf(a - b)));
}
// lc = -softplus(k), lsig = -softplus(-k); share log1p(e^-|k|).
__device__ __forceinline__ void lc_lsig(float k, float& lc, float& lsig) {
    float L = __logf(1.f + __expf(-fabsf(k)));
    lc   = -fmaxf(k, 0.f)  - L;
    lsig = -fmaxf(-k, 0.f) - L;
}

// ===========================================================================
// fp16 convert kernel: x (4,194,304 float4) then [Wz;Wh] (524,288 float4)
// ===========================================================================
__global__ void cvt_kernel(const float4* __restrict__ x,
                           const float4* __restrict__ Wz,
                           const float4* __restrict__ Wh)
{
    int i = blockIdx.x * blockDim.x + threadIdx.x;   // < 4718592
    float4 v;
    uint2* dst;
    if (i < 4194304) {
        v = x[i];
        dst = (uint2*)gx + i;
    } else {
        int j = i - 4194304;                          // 0..524287
        v = (j < 262144) ? Wz[j] : Wh[j - 262144];
        dst = (uint2*)gw + j;
    }
    union { __half h[4]; uint2 u; } o;
    o.h[0] = __float2half_rn(v.x); o.h[1] = __float2half_rn(v.y);
    o.h[2] = __float2half_rn(v.z); o.h[3] = __float2half_rn(v.w);
    *dst = o.u;
}

// ===========================================================================
// fp16 MMA GEMM + fused epilogue (g_lcv + chunk summaries g_A/g_R).
// B-tile row r (0..127): j = r>>5 selects the warp-column's 16-wide h block,
// w = r&31: w<16 -> Wz row (n0*64 + j*16 + w), w>=16 -> Wh row (same h).
// ===========================================================================
__device__ __forceinline__ void load_tile(
    int kt, uint32_t sbase, int m0, int n0, int tid)
{
    int kk = kt << 6;                       // fp16 column offset
    uint32_t bB = sbase + A_BYTES;
#pragma unroll
    for (int i = 0; i < 4; i++) {           // A: 256 rows x 8 chunks
        int idx = i * 512 + tid;
        int r = idx >> 3, c = idx & 7;
        uint32_t dst = sbase + r * 128 + ((c ^ (r & 7)) << 4);
        cp_async16(dst, gx + (((size_t)(m0 + r)) << 10) + kk + (c << 3));
    }
#pragma unroll
    for (int i = 0; i < 2; i++) {           // B: 128 rows x 8 chunks
        int idx = i * 512 + tid;
        int r = idx >> 3, c = idx & 7;
        int j = r >> 5, w = r & 31;
        int grow = (w < 16) ? (n0 * 64 + j * 16 + w)
                            : (1024 + n0 * 64 + j * 16 + (w - 16));
        uint32_t dst = bB + r * 128 + ((c ^ (r & 7)) << 4);
        cp_async16(dst, gw + (((size_t)grow) << 10) + kk + (c << 3));
    }
}

__global__ void __launch_bounds__(512, 1) gemm_mma_kernel(
    const float* __restrict__ bz_g, const float* __restrict__ bh_g)
{
    extern __shared__ __align__(1024) char sm[];
    const uint32_t smem_base = smem_u32(sm);
    const int tid = threadIdx.x;
    const int lane = tid & 31;
    const int wid = tid >> 5;
    const int warp_m = wid >> 2;       // 0..3 : 64-row M quarter
    const int warp_j = wid & 3;        // 0..3 : 32-row N block (16 h)
    const int n0 = blockIdx.x;         // 0..15
    const int m0 = blockIdx.y * BM;

    // barriers: full[s] = SM_BAR + s*8 (count 512, cp.async completions);
    //           empty[s] = SM_BAR + 32 + s*8 (count 16, warp arrivals)
    if (tid == 0) {
#pragma unroll
        for (int s = 0; s < STAGES; s++) {
            mbar_init(smem_base + SM_BAR + s * 8, 512);
            mbar_init(smem_base + SM_BAR + 32 + s * 8, 16);
        }
    }
    __syncthreads();

    float acc[4][4][4];
#pragma unroll
    for (int a = 0; a < 4; a++)
#pragma unroll
        for (int b = 0; b < 4; b++)
#pragma unroll
            for (int c = 0; c < 4; c++) acc[a][b][c] = 0.f;

#pragma unroll
    for (int s = 0; s < 3; s++) {
        load_tile(s, smem_base + s * STAGE_BYTES, m0, n0, tid);
        cp_async_mbar_arrive(smem_base + SM_BAR + s * 8);
    }

    const int a_row = lane & 15;       // m within 16-tile
    const int a_ch  = lane >> 4;       // k half (chunk select)
    const int b_row = lane & 7;        // n within 8-tile
    const int b_kh  = (lane >> 3) & 1; // k half (chunk select)
    const int b_td  = lane >> 4;       // n8 tile within pair

    for (int kt = 0; kt < NTILES; ++kt) {
        // ---- producer: tile kt+3 into stage (kt+3)%4 ----
        int kp = kt + 3;
        if (kp < NTILES) {
            int sp = kp & 3;
            int qp = kp >> 2;
            if (qp >= 1)               // stage reused: wait compute of kp-4
                mbar_wait(smem_base + SM_BAR + 32 + sp * 8,
                          (uint32_t)((qp - 1) & 1));
            load_tile(kp, smem_base + sp * STAGE_BYTES, m0, n0, tid);
            cp_async_mbar_arrive(smem_base + SM_BAR + sp * 8);
        }

        // ---- consumer: tile kt from stage kt%4 ----
        int s = kt & 3;
        mbar_wait(smem_base + SM_BAR + s * 8, (uint32_t)((kt >> 2) & 1));

        const uint32_t aB = smem_base + s * STAGE_BYTES;
        const uint32_t bB = aB + A_BYTES;
#pragma unroll
        for (int ks = 0; ks < 4; ks++) {   // 4 k16 steps per 64-fp16 tile
            uint32_t af[4][4];
#pragma unroll
            for (int mt = 0; mt < 4; mt++) {
                int r = warp_m * 64 + mt * 16 + a_row;
                int ch = (ks * 2 + a_ch) ^ (r & 7);
                LDSM_X4(af[mt][0], af[mt][1], af[mt][2], af[mt][3],
                        aB + r * 128 + ch * 16);
            }
            uint32_t bf[4][2];
#pragma unroll
            for (int tp = 0; tp < 2; tp++) {
                int r = warp_j * 32 + tp * 16 + b_td * 8 + b_row;
                int ch = (ks * 2 + b_kh) ^ (r & 7);
                LDSM_X4(bf[tp * 2][0], bf[tp * 2][1],
                        bf[tp * 2 + 1][0], bf[tp * 2 + 1][1],
                        bB + r * 128 + ch * 16);
            }
#pragma unroll
            for (int mt = 0; mt < 4; mt++)
#pragma unroll
                for (int t = 0; t < 4; t++)
                    mma_f16(acc[mt][t], af[mt], bf[t]);
        }
        __syncwarp();
        if (lane == 0) mbar_arrive(smem_base + SM_BAR + 32 + s * 8);
    }

    // ---------------- fused epilogue (in-register) ------------------------
    // t = 0..1 hold k, t = 2..3 hold h~ for the same h coordinates.
    // Writes g_lcv AND stores (lc,lv) into the smem transpose tile for the
    // fused chunk-summary pass (pipeline smem is dead now; sync first).
    __syncthreads();                       // all stages consumed; alias smem
    float2* tp = (float2*)sm;              // [256][TP_STRIDE]

    const int gr = lane >> 2;            // 0..7  (row in m16 tile)
    const int gc = (lane & 3) << 1;      // 0,2,4,6 (col pair)
#pragma unroll
    for (int t = 0; t < 2; t++) {
        int hloc = warp_j * 16 + t * 8 + gc;     // local h 0..63
        int h = n0 * 64 + hloc;
        float bz0 = __ldg(bz_g + h),     bz1 = __ldg(bz_g + h + 1);
        float bh0 = __ldg(bh_g + h),     bh1 = __ldg(bh_g + h + 1);
#pragma unroll
        for (int mt = 0; mt < 4; mt++) {
            int rloc = warp_m * 64 + mt * 16 + gr;   // local t row 0..255
            int r0 = m0 + rloc;
            const float* ck = acc[mt][t];
            const float* ch = acc[mt][t + 2];
#pragma unroll
            for (int rr = 0; rr < 2; rr++) {
                float k0 = ck[rr * 2 + 0] + bz0;
                float k1 = ck[rr * 2 + 1] + bz1;
                float t0 = ch[rr * 2 + 0] + bh0;
                float t1 = ch[rr * 2 + 1] + bh1;
                float4 o;
                float ls0, ls1;
                lc_lsig(k0, o.x, ls0);
                lc_lsig(k1, o.z, ls1);
                o.y = ls0 + log_g_f(t0);
                o.w = ls1 + log_g_f(t1);
                *(float4*)((float*)g_lcv +
                           (((size_t)(r0 + rr * 8)) * Hc + h) * 2) = o;
                float2* row = tp + (rloc + rr * 8) * TP_STRIDE + hloc;
                row[0] = make_float2(o.x, o.y);
                row[1] = make_float2(o.z, o.w);
            }
        }
    }

    // ---------------- fused chunk summaries -------------------------------
    // 8 chunks x 64 h = 512 threads; each scans 32 sequential t in smem.
    __syncthreads();
    {
        int c  = tid >> 6;                 // 0..7 local chunk
        int hl = tid & 63;                 // local h
        const float2* p = tp + (c * CLEN) * TP_STRIDE + hl;
        float A = 0.f, R = -INFINITY;
#pragma unroll 4
        for (int t = 0; t < CLEN; t++) {
            float2 v = *p; p += TP_STRIDE;
            R = logaddexp_f(R + v.x, v.y);
            A += v.x;
        }
        int bb = m0 >> 12;                               // batch
        int cg = ((m0 & (Tc - 1)) >> 5) + c;             // global chunk
        int idx = cg * BHc + bb * Hc + n0 * 64 + hl;
        g_A[idx] = A;
        g_R[idx] = R;
    }
}

// ===========================================================================
// warp-parallel combine: 1 warp per chain; lane handles chunks 4L..4L+3;
// compose(P then Q) = (P.A + Q.A, logaddexp(P.R + Q.A, Q.R)).
// ===========================================================================
__global__ void scan_combine_kernel(const float* __restrict__ h0)
{
    int gt = blockIdx.x * blockDim.x + threadIdx.x;
    int w = gt >> 5;                   // chain id < 4096
    int lane = gt & 31;
    float lh0 = log_g_f(__ldg(h0 + w));
    int i0 = (lane * 4) * BHc + w;
    float Al[4], Rl[4];
#pragma unroll
    for (int k = 0; k < 4; k++) {
        Al[k] = g_A[i0 + k * BHc];
        Rl[k] = g_R[i0 + k * BHc];
    }
    float Ai = Al[0], Ri = Rl[0];
#pragma unroll
    for (int k = 1; k < 4; k++) {
        Ri = logaddexp_f(Ri + Al[k], Rl[k]);
        Ai = Ai + Al[k];
    }
#pragma unroll
    for (int d = 1; d < 32; d <<= 1) {
        float Au = __shfl_up_sync(0xFFFFFFFFu, Ai, d);
        float Ru = __shfl_up_sync(0xFFFFFFFFu, Ri, d);
        if (lane >= d) {
            Ri = logaddexp_f(Ru + Ai, Ri);
            Ai = Au + Ai;
        }
    }
    float Ae = __shfl_up_sync(0xFFFFFFFFu, Ai, 1);
    float Re = __shfl_up_sync(0xFFFFFFFFu, Ri, 1);
    if (lane == 0) { Ae = 0.f; Re = -INFINITY; }
#pragma unroll
    for (int k = 0; k < 4; k++) {
        g_hin[i0 + k * BHc] = logaddexp_f(Ae + lh0, Re);
        Re = logaddexp_f(Re + Al[k], Rl[k]);
        Ae = Ae + Al[k];
    }
}

// ===========================================================================
// final pass: lh <- logaddexp(lh + lc, lv); out = exp(lh)
// 4 h-adjacent chains per thread, 2 independent float4 loads per step.
// ===========================================================================
__global__ void scan_final_kernel(float* __restrict__ out)
{
    int g = blockIdx.x * blockDim.x + threadIdx.x;   // < NCHUNK * BHc / 4
    int p = g & (BHc / 4 - 1);
    int c = g >> 10;
    int b = p >> 8;
    int h = (p & 255) << 2;
    size_t base = ((size_t)b * Tc + (size_t)c * CLEN) * Hc + h;
    int idx = c * BHc + b * Hc + h;
    float lh0 = g_hin[idx],     lh1 = g_hin[idx + 1];
    float lh2 = g_hin[idx + 2], lh3 = g_hin[idx + 3];
#pragma unroll 4
    for (int t = 0; t < CLEN; t++) {
        float4 u = *(const float4*)&g_lcv[base];
        float4 v = *(const float4*)&g_lcv[base + 2];
        lh0 = logaddexp_f(lh0 + u.x, u.y);
        lh1 = logaddexp_f(lh1 + u.z, u.w);
        lh2 = logaddexp_f(lh2 + v.x, v.y);
        lh3 = logaddexp_f(lh3 + v.z, v.w);
        float4 o;
        o.x = __expf(lh0); o.y = __expf(lh1);
        o.z = __expf(lh2); o.w = __expf(lh3);
        *(float4*)&out[base] = o;
        base += Hc;
    }
}

// ===========================================================================
extern "C" void kernel_launch(void* const* d_in, const int* in_sizes, int n_in,
                              void* d_out, int out_size)
{
    const float* x  = (const float*)d_in[0];
    const float* h0 = (const float*)d_in[1];
    const float* Wz = (const float*)d_in[2];
    const float* bz = (const float*)d_in[3];
    const float* Wh = (const float*)d_in[4];
    const float* bh = (const float*)d_in[5];
    float* out = (float*)d_out;

    cudaFuncSetAttribute(gemm_mma_kernel,
                         cudaFuncAttributeMaxDynamicSharedMemorySize, SMEM_TOTAL);

    cvt_kernel<<<18432, 256>>>((const float4*)x, (const float4*)Wz,
                               (const float4*)Wh);

    dim3 ggrid(Hc / 64, (Bc * Tc) / BM);   // (16, 128)
    gemm_mma_kernel<<<ggrid, 512, SMEM_TOTAL>>>(bz, bh);

    scan_combine_kernel<<<(BHc * 32) / 256, 256>>>(h0);
    scan_final_kernel<<<(NCHUNK * BHc / 4) / 256, 256>>>(out);
}

// round 16
// speedup vs baseline: 1.0787x; 1.0787x over previous
#include <cuda_runtime.h>
#include <cuda_fp16.h>
#include <math.h>
#include <stdint.h>

// ---------------- problem dims -------------------------------------------
#define Bc 4
#define Tc 4096
#define Dc 1024
#define Hc 1024
#define BHc (Bc * Hc)
#define NCHUNK 128
#define CLEN (Tc / NCHUNK)       // 32

// ---------------- GEMM geometry ------------------------------------------
// fp16 single-pass GEMM, mbarrier pipeline, fused log-space epilogue AND
// fused per-chunk scan summaries (each CTA owns 4 complete 32-t chunks).
// CTA tile 128x128, 256 threads (8 warps), warp tile 64M x 32N, 2 CTAs/SM.
#define BM 128
#define BN 128
#define NTILES 16                // K = 1024
#define STAGES 3
#define A_BYTES (BM * 128)       // 16384
#define B_BYTES (BN * 128)       // 16384
#define STAGE_BYTES (A_BYTES + B_BYTES)   // 32768
#define SM_BAR (STAGES * STAGE_BYTES)     // 98304
#define SMEM_TOTAL (SM_BAR + 64)          // 98368 per CTA (2 fit/SM)
// epilogue transpose tile aliases the pipeline buffers: [128][67] float2
#define TP_STRIDE 67                      // float2 units; 128*67*8 = 68608 B

// ---------------- scratch globals ----------------------------------------
__device__ __align__(1024) __half gx[(size_t)Bc * Tc * Dc];    // fp16 x
__device__ __align__(1024) __half gw[2048 * 1024];             // fp16 [Wz;Wh]
__device__ float2 g_lcv[(size_t)Bc * Tc * Hc];                 // (lc, lv)
__device__ float g_A[NCHUNK * BHc];
__device__ float g_R[NCHUNK * BHc];
__device__ float g_hin[NCHUNK * BHc];

// ---------------- PTX helpers --------------------------------------------
__device__ __forceinline__ uint32_t smem_u32(const void* p) {
    uint32_t a;
    asm("{ .reg .u64 t; cvta.to.shared.u64 t, %1; cvt.u32.u64 %0, t; }"
        : "=r"(a) : "l"(p));
    return a;
}
__device__ __forceinline__ void cp_async16(uint32_t dst, const void* src) {
    asm volatile("cp.async.cg.shared.global [%0], [%1], 16;"
                 :: "r"(dst), "l"(src) : "memory");
}
__device__ __forceinline__ void mbar_init(uint32_t a, uint32_t cnt) {
    asm volatile("mbarrier.init.shared.b64 [%0], %1;" :: "r"(a), "r"(cnt) : "memory");
}
__device__ __forceinline__ void mbar_arrive(uint32_t a) {
    asm volatile("{ .reg .b64 t; mbarrier.arrive.shared.b64 t, [%0]; }"
                 :: "r"(a) : "memory");
}
__device__ __forceinline__ void cp_async_mbar_arrive(uint32_t a) {
    asm volatile("cp.async.mbarrier.arrive.noinc.shared.b64 [%0];"
                 :: "r"(a) : "memory");
}
__device__ __forceinline__ void mbar_wait(uint32_t a, uint32_t parity) {
    asm volatile(
        "{\n\t.reg .pred P;\n"
        "W_%=:\n\t"
        "mbarrier.try_wait.parity.shared.b64 P, [%0], %1;\n\t"
        "@P bra.uni D_%=;\n\t"
        "bra.uni W_%=;\n\t"
        "D_%=:\n\t}" :: "r"(a), "r"(parity) : "memory");
}

#define LDSM_X4(r0, r1, r2, r3, addr) \
    asm volatile("ldmatrix.sync.aligned.m8n8.x4.shared.b16 {%0,%1,%2,%3}, [%4];" \
                 : "=r"(r0), "=r"(r1), "=r"(r2), "=r"(r3) : "r"(addr))

__device__ __forceinline__ void mma_f16(float* c, const uint32_t* a,
                                        const uint32_t* b) {
    asm volatile(
        "mma.sync.aligned.m16n8k16.row.col.f32.f16.f16.f32 "
        "{%0,%1,%2,%3}, {%4,%5,%6,%7}, {%8,%9}, {%0,%1,%2,%3};"
        : "+f"(c[0]), "+f"(c[1]), "+f"(c[2]), "+f"(c[3])
        : "r"(a[0]), "r"(a[1]), "r"(a[2]), "r"(a[3]), "r"(b[0]), "r"(b[1]));
}

// ---------------- math helpers -------------------------------------------
__device__ __forceinline__ float softplus_f(float u) {
    return fmaxf(u, 0.f) + __logf(1.f + __expf(-fabsf(u)));
}
__device__ __forceinline__ float log_g_f(float v) {
    return (v >= 0.f) ? __logf(v + 0.5f) : -softplus_f(-v);
}
__device__ __forceinline__ float logaddexp_f(float a, float b) {
    float m = fmaxf(a, b);
    if (m == -INFINITY) return -INFINITY;
    return m + __logf(1.f + __expf(-fabsf(a - b)));
}
// lc = -softplus(k), lsig = -softplus(-k); share log1p(e^-|k|).
__device__ __forceinline__ void lc_lsig(float k, float& lc, float& lsig) {
    float L = __logf(1.f + __expf(-fabsf(k)));
    lc   = -fmaxf(k, 0.f)  - L;
    lsig = -fmaxf(-k, 0.f) - L;
}

// ===========================================================================
// fp16 convert kernel: x (4,194,304 float4) then [Wz;Wh] (524,288 float4)
// ===========================================================================
__global__ void cvt_kernel(const float4* __restrict__ x,
                           const float4* __restrict__ Wz,
                           const float4* __restrict__ Wh)
{
    int i = blockIdx.x * blockDim.x + threadIdx.x;   // < 4718592
    float4 v;
    uint2* dst;
    if (i < 4194304) {
        v = __ldcs(x + i);
        dst = (uint2*)gx + i;
    } else {
        int j = i - 4194304;                          // 0..524287
        v = (j < 262144) ? __ldcs(Wz + j) : __ldcs(Wh + (j - 262144));
        dst = (uint2*)gw + j;
    }
    union { __half h[4]; uint2 u; } o;
    o.h[0] = __float2half_rn(v.x); o.h[1] = __float2half_rn(v.y);
    o.h[2] = __float2half_rn(v.z); o.h[3] = __float2half_rn(v.w);
    *dst = o.u;
}

// ===========================================================================
// fp16 MMA GEMM + fused epilogue (g_lcv + chunk summaries g_A/g_R).
// B-tile row r (0..127): j = r>>5 selects the warp-column's 16-wide h block,
// w = r&31: w<16 -> Wz row (n0*64 + j*16 + w), w>=16 -> Wh row (same h).
// ===========================================================================
__device__ __forceinline__ void load_tile(
    int kt, uint32_t sbase, int m0, int n0, int tid)
{
    int kk = kt << 6;                       // fp16 column offset
    uint32_t bB = sbase + A_BYTES;
#pragma unroll
    for (int i = 0; i < 4; i++) {           // A: 128 rows x 8 chunks
        int idx = i * 256 + tid;
        int r = idx >> 3, c = idx & 7;
        uint32_t dst = sbase + r * 128 + ((c ^ (r & 7)) << 4);
        cp_async16(dst, gx + (((size_t)(m0 + r)) << 10) + kk + (c << 3));
    }
#pragma unroll
    for (int i = 0; i < 4; i++) {           // B: 128 rows x 8 chunks
        int idx = i * 256 + tid;
        int r = idx >> 3, c = idx & 7;
        int j = r >> 5, w = r & 31;
        int grow = (w < 16) ? (n0 * 64 + j * 16 + w)
                            : (1024 + n0 * 64 + j * 16 + (w - 16));
        uint32_t dst = bB + r * 128 + ((c ^ (r & 7)) << 4);
        cp_async16(dst, gw + (((size_t)grow) << 10) + kk + (c << 3));
    }
}

__global__ void __launch_bounds__(256, 2) gemm_mma_kernel(
    const float* __restrict__ bz_g, const float* __restrict__ bh_g)
{
    extern __shared__ __align__(1024) char sm[];
    const uint32_t smem_base = smem_u32(sm);
    const int tid = threadIdx.x;
    const int lane = tid & 31;
    const int wid = tid >> 5;
    const int warp_m = wid >> 2;       // 0..1 : 64-row M half
    const int warp_j = wid & 3;        // 0..3 : 32-row N block (16 h)
    const int n0 = blockIdx.x;         // 0..15
    const int m0 = blockIdx.y * BM;

    // barriers: full[s] = SM_BAR + s*8 (count 256, cp.async completions);
    //           empty[s] = SM_BAR + 24 + s*8 (count 8, warp arrivals)
    if (tid == 0) {
#pragma unroll
        for (int s = 0; s < STAGES; s++) {
            mbar_init(smem_base + SM_BAR + s * 8, 256);
            mbar_init(smem_base + SM_BAR + 24 + s * 8, 8);
        }
    }
    __syncthreads();

    float acc[4][4][4];
#pragma unroll
    for (int a = 0; a < 4; a++)
#pragma unroll
        for (int b = 0; b < 4; b++)
#pragma unroll
            for (int c = 0; c < 4; c++) acc[a][b][c] = 0.f;

    load_tile(0, smem_base + 0 * STAGE_BYTES, m0, n0, tid);
    cp_async_mbar_arrive(smem_base + SM_BAR + 0 * 8);
    load_tile(1, smem_base + 1 * STAGE_BYTES, m0, n0, tid);
    cp_async_mbar_arrive(smem_base + SM_BAR + 1 * 8);

    const int a_row = lane & 15;       // m within 16-tile
    const int a_ch  = lane >> 4;       // k half (chunk select)
    const int b_row = lane & 7;        // n within 8-tile
    const int b_kh  = (lane >> 3) & 1; // k half (chunk select)
    const int b_td  = lane >> 4;       // n8 tile within pair

    for (int kt = 0; kt < NTILES; ++kt) {
        // ---- producer: tile kt+2 into stage (kt+2)%3 ----
        int kp = kt + 2;
        if (kp < NTILES) {
            int sp = kp % STAGES;
            int qp = kp / STAGES;
            if (qp >= 1)               // stage reused: wait compute of kp-3
                mbar_wait(smem_base + SM_BAR + 24 + sp * 8,
                          (uint32_t)((qp - 1) & 1));
            load_tile(kp, smem_base + sp * STAGE_BYTES, m0, n0, tid);
            cp_async_mbar_arrive(smem_base + SM_BAR + sp * 8);
        }

        // ---- consumer: tile kt from stage kt%3 ----
        int s = kt % STAGES;
        mbar_wait(smem_base + SM_BAR + s * 8, (uint32_t)((kt / STAGES) & 1));

        const uint32_t aB = smem_base + s * STAGE_BYTES;
        const uint32_t bB = aB + A_BYTES;
#pragma unroll
        for (int ks = 0; ks < 4; ks++) {   // 4 k16 steps per 64-fp16 tile
            uint32_t af[4][4];
#pragma unroll
            for (int mt = 0; mt < 4; mt++) {
                int r = warp_m * 64 + mt * 16 + a_row;
                int ch = (ks * 2 + a_ch) ^ (r & 7);
                LDSM_X4(af[mt][0], af[mt][1], af[mt][2], af[mt][3],
                        aB + r * 128 + ch * 16);
            }
            uint32_t bf[4][2];
#pragma unroll
            for (int tp = 0; tp < 2; tp++) {
                int r = warp_j * 32 + tp * 16 + b_td * 8 + b_row;
                int ch = (ks * 2 + b_kh) ^ (r & 7);
                LDSM_X4(bf[tp * 2][0], bf[tp * 2][1],
                        bf[tp * 2 + 1][0], bf[tp * 2 + 1][1],
                        bB + r * 128 + ch * 16);
            }
#pragma unroll
            for (int mt = 0; mt < 4; mt++)
#pragma unroll
                for (int t = 0; t < 4; t++)
                    mma_f16(acc[mt][t], af[mt], bf[t]);
        }
        __syncwarp();
        if (lane == 0) mbar_arrive(smem_base + SM_BAR + 24 + s * 8);
    }

    // ---------------- fused epilogue (in-register) ------------------------
    // t = 0..1 hold k, t = 2..3 hold h~ for the same h coordinates.
    // Writes g_lcv AND stores (lc,lv) into the smem transpose tile for the
    // fused chunk-summary pass (pipeline smem is dead now; sync first).
    __syncthreads();                       // all stages consumed; alias smem
    float2* tp = (float2*)sm;              // [128][TP_STRIDE]

    const int gr = lane >> 2;            // 0..7  (row in m16 tile)
    const int gc = (lane & 3) << 1;      // 0,2,4,6 (col pair)
#pragma unroll
    for (int t = 0; t < 2; t++) {
        int hloc = warp_j * 16 + t * 8 + gc;     // local h 0..63
        int h = n0 * 64 + hloc;
        float bz0 = __ldg(bz_g + h),     bz1 = __ldg(bz_g + h + 1);
        float bh0 = __ldg(bh_g + h),     bh1 = __ldg(bh_g + h + 1);
#pragma unroll
        for (int mt = 0; mt < 4; mt++) {
            int rloc = warp_m * 64 + mt * 16 + gr;   // local t row
            int r0 = m0 + rloc;
            const float* ck = acc[mt][t];
            const float* ch = acc[mt][t + 2];
#pragma unroll
            for (int rr = 0; rr < 2; rr++) {
                float k0 = ck[rr * 2 + 0] + bz0;
                float k1 = ck[rr * 2 + 1] + bz1;
                float t0 = ch[rr * 2 + 0] + bh0;
                float t1 = ch[rr * 2 + 1] + bh1;
                float4 o;
                float ls0, ls1;
                lc_lsig(k0, o.x, ls0);
                lc_lsig(k1, o.z, ls1);
                o.y = ls0 + log_g_f(t0);
                o.w = ls1 + log_g_f(t1);
                *(float4*)((float*)g_lcv +
                           (((size_t)(r0 + rr * 8)) * Hc + h) * 2) = o;
                float2* row = tp + (rloc + rr * 8) * TP_STRIDE + hloc;
                row[0] = make_float2(o.x, o.y);
                row[1] = make_float2(o.z, o.w);
            }
        }
    }

    // ---------------- fused chunk summaries -------------------------------
    // 4 chunks x 64 h = 256 threads; each scans 32 sequential t in smem.
    __syncthreads();
    {
        int c  = tid >> 6;                 // 0..3 local chunk
        int hl = tid & 63;                 // local h
        const float2* p = tp + (c * CLEN) * TP_STRIDE + hl;
        float A = 0.f, R = -INFINITY;
#pragma unroll 4
        for (int t = 0; t < CLEN; t++) {
            float2 v = *p; p += TP_STRIDE;
            R = logaddexp_f(R + v.x, v.y);
            A += v.x;
        }
        int bb = m0 >> 12;                               // batch
        int cg = ((m0 & (Tc - 1)) >> 5) + c;             // global chunk
        int idx = cg * BHc + bb * Hc + n0 * 64 + hl;
        g_A[idx] = A;
        g_R[idx] = R;
    }
}

// ===========================================================================
// warp-parallel combine: 1 warp per chain; lane handles chunks 4L..4L+3;
// compose(P then Q) = (P.A + Q.A, logaddexp(P.R + Q.A, Q.R)).
// ===========================================================================
__global__ void scan_combine_kernel(const float* __restrict__ h0)
{
    int gt = blockIdx.x * blockDim.x + threadIdx.x;
    int w = gt >> 5;                   // chain id < 4096
    int lane = gt & 31;
    float lh0 = log_g_f(__ldg(h0 + w));
    int i0 = (lane * 4) * BHc + w;
    float Al[4], Rl[4];
#pragma unroll
    for (int k = 0; k < 4; k++) {
        Al[k] = g_A[i0 + k * BHc];
        Rl[k] = g_R[i0 + k * BHc];
    }
    float Ai = Al[0], Ri = Rl[0];
#pragma unroll
    for (int k = 1; k < 4; k++) {
        Ri = logaddexp_f(Ri + Al[k], Rl[k]);
        Ai = Ai + Al[k];
    }
#pragma unroll
    for (int d = 1; d < 32; d <<= 1) {
        float Au = __shfl_up_sync(0xFFFFFFFFu, Ai, d);
        float Ru = __shfl_up_sync(0xFFFFFFFFu, Ri, d);
        if (lane >= d) {
            Ri = logaddexp_f(Ru + Ai, Ri);
            Ai = Au + Ai;
        }
    }
    float Ae = __shfl_up_sync(0xFFFFFFFFu, Ai, 1);
    float Re = __shfl_up_sync(0xFFFFFFFFu, Ri, 1);
    if (lane == 0) { Ae = 0.f; Re = -INFINITY; }
#pragma unroll
    for (int k = 0; k < 4; k++) {
        g_hin[i0 + k * BHc] = logaddexp_f(Ae + lh0, Re);
        Re = logaddexp_f(Re + Al[k], Rl[k]);
        Ae = Ae + Al[k];
    }
}

// ===========================================================================
// final pass: lh <- logaddexp(lh + lc, lv); out = exp(lh)
// 8 h-adjacent chains per thread, 4 independent float4 loads per step
// (streaming loads/stores: data is touched exactly once here).
// ===========================================================================
__global__ void scan_final_kernel(float* __restrict__ out)
{
    int g = blockIdx.x * blockDim.x + threadIdx.x;   // < NCHUNK * BHc / 8
    int p = g & (BHc / 8 - 1);
    int c = g >> 9;
    int b = p >> 7;
    int h = (p & 127) << 3;
    size_t base = ((size_t)b * Tc + (size_t)c * CLEN) * Hc + h;
    int idx = c * BHc + b * Hc + h;
    float lh0 = g_hin[idx],     lh1 = g_hin[idx + 1];
    float lh2 = g_hin[idx + 2], lh3 = g_hin[idx + 3];
    float lh4 = g_hin[idx + 4], lh5 = g_hin[idx + 5];
    float lh6 = g_hin[idx + 6], lh7 = g_hin[idx + 7];
#pragma unroll 4
    for (int t = 0; t < CLEN; t++) {
        float4 u = __ldcs((const float4*)&g_lcv[base]);
        float4 v = __ldcs((const float4*)&g_lcv[base + 2]);
        float4 w = __ldcs((const float4*)&g_lcv[base + 4]);
        float4 z = __ldcs((const float4*)&g_lcv[base + 6]);
        lh0 = logaddexp_f(lh0 + u.x, u.y);
        lh1 = logaddexp_f(lh1 + u.z, u.w);
        lh2 = logaddexp_f(lh2 + v.x, v.y);
        lh3 = logaddexp_f(lh3 + v.z, v.w);
        lh4 = logaddexp_f(lh4 + w.x, w.y);
        lh5 = logaddexp_f(lh5 + w.z, w.w);
        lh6 = logaddexp_f(lh6 + z.x, z.y);
        lh7 = logaddexp_f(lh7 + z.z, z.w);
        float4 o1, o2;
        o1.x = __expf(lh0); o1.y = __expf(lh1);
        o1.z = __expf(lh2); o1.w = __expf(lh3);
        o2.x = __expf(lh4); o2.y = __expf(lh5);
        o2.z = __expf(lh6); o2.w = __expf(lh7);
        __stcs((float4*)&out[base], o1);
        __stcs((float4*)&out[base + 4], o2);
        base += Hc;
    }
}

// ===========================================================================
extern "C" void kernel_launch(void* const* d_in, const int* in_sizes, int n_in,
                              void* d_out, int out_size)
{
    const float* x  = (const float*)d_in[0];
    const float* h0 = (const float*)d_in[1];
    const float* Wz = (const float*)d_in[2];
    const float* bz = (const float*)d_in[3];
    const float* Wh = (const float*)d_in[4];
    const float* bh = (const float*)d_in[5];
    float* out = (float*)d_out;

    cudaFuncSetAttribute(gemm_mma_kernel,
                         cudaFuncAttributeMaxDynamicSharedMemorySize, SMEM_TOTAL);

    cvt_kernel<<<18432, 256>>>((const float4*)x, (const float4*)Wz,
                               (const float4*)Wh);

    dim3 ggrid(Hc / 64, (Bc * Tc) / BM);   // (16, 128)
    gemm_mma_kernel<<<ggrid, 256, SMEM_TOTAL>>>(bz, bh);

    scan_combine_kernel<<<(BHc * 32) / 256, 256>>>(h0);
    scan_final_kernel<<<(NCHUNK * BHc / 8) / 256, 256>>>(out);
}

// round 17
// speedup vs baseline: 1.1157x; 1.0343x over previous
#include <cuda_runtime.h>
#include <cuda_fp16.h>
#include <math.h>
#include <stdint.h>

// ---------------- problem dims -------------------------------------------
#define Bc 4
#define Tc 4096
#define Dc 1024
#define Hc 1024
#define BHc (Bc * Hc)
#define NCHUNK 128
#define CLEN (Tc / NCHUNK)       // 32

// ---------------- GEMM geometry ------------------------------------------
// fp16 single-pass GEMM, mbarrier pipeline, fused log-space epilogue AND
// fused per-chunk scan summaries (each CTA owns 4 complete 32-t chunks).
// CTA tile 128x128, 256 threads (8 warps), warp tile 64M x 32N, 2 CTAs/SM.
#define BM 128
#define BN 128
#define NTILES 16                // K = 1024
#define STAGES 3
#define A_BYTES (BM * 128)       // 16384
#define B_BYTES (BN * 128)       // 16384
#define STAGE_BYTES (A_BYTES + B_BYTES)   // 32768
#define SM_BAR (STAGES * STAGE_BYTES)     // 98304
#define SMEM_TOTAL (SM_BAR + 64)          // 98368 per CTA (2 fit/SM)
// epilogue transpose tile aliases the pipeline buffers: [128][67] float2
#define TP_STRIDE 67                      // float2 units; 128*67*8 = 68608 B

// ---------------- scratch globals ----------------------------------------
__device__ __align__(1024) __half gx[(size_t)Bc * Tc * Dc];    // fp16 x
__device__ __align__(1024) __half gw[2048 * 1024];             // fp16 [Wz;Wh]
__device__ float2 g_lcv[(size_t)Bc * Tc * Hc];                 // (lc, lv)
__device__ float g_A[NCHUNK * BHc];
__device__ float g_R[NCHUNK * BHc];
__device__ float g_hin[NCHUNK * BHc];

// ---------------- PTX helpers --------------------------------------------
__device__ __forceinline__ uint32_t smem_u32(const void* p) {
    uint32_t a;
    asm("{ .reg .u64 t; cvta.to.shared.u64 t, %1; cvt.u32.u64 %0, t; }"
        : "=r"(a) : "l"(p));
    return a;
}
__device__ __forceinline__ void cp_async16(uint32_t dst, const void* src) {
    asm volatile("cp.async.cg.shared.global [%0], [%1], 16;"
                 :: "r"(dst), "l"(src) : "memory");
}
__device__ __forceinline__ void mbar_init(uint32_t a, uint32_t cnt) {
    asm volatile("mbarrier.init.shared.b64 [%0], %1;" :: "r"(a), "r"(cnt) : "memory");
}
__device__ __forceinline__ void mbar_arrive(uint32_t a) {
    asm volatile("{ .reg .b64 t; mbarrier.arrive.shared.b64 t, [%0]; }"
                 :: "r"(a) : "memory");
}
__device__ __forceinline__ void cp_async_mbar_arrive(uint32_t a) {
    asm volatile("cp.async.mbarrier.arrive.noinc.shared.b64 [%0];"
                 :: "r"(a) : "memory");
}
__device__ __forceinline__ void mbar_wait(uint32_t a, uint32_t parity) {
    asm volatile(
        "{\n\t.reg .pred P;\n"
        "W_%=:\n\t"
        "mbarrier.try_wait.parity.shared.b64 P, [%0], %1;\n\t"
        "@P bra.uni D_%=;\n\t"
        "bra.uni W_%=;\n\t"
        "D_%=:\n\t}" :: "r"(a), "r"(parity) : "memory");
}

#define LDSM_X4(r0, r1, r2, r3, addr) \
    asm volatile("ldmatrix.sync.aligned.m8n8.x4.shared.b16 {%0,%1,%2,%3}, [%4];" \
                 : "=r"(r0), "=r"(r1), "=r"(r2), "=r"(r3) : "r"(addr))

__device__ __forceinline__ void mma_f16(float* c, const uint32_t* a,
                                        const uint32_t* b) {
    asm volatile(
        "mma.sync.aligned.m16n8k16.row.col.f32.f16.f16.f32 "
        "{%0,%1,%2,%3}, {%4,%5,%6,%7}, {%8,%9}, {%0,%1,%2,%3};"
        : "+f"(c[0]), "+f"(c[1]), "+f"(c[2]), "+f"(c[3])
        : "r"(a[0]), "r"(a[1]), "r"(a[2]), "r"(a[3]), "r"(b[0]), "r"(b[1]));
}

// ---------------- math helpers -------------------------------------------
__device__ __forceinline__ float softplus_f(float u) {
    return fmaxf(u, 0.f) + __logf(1.f + __expf(-fabsf(u)));
}
__device__ __forceinline__ float log_g_f(float v) {
    return (v >= 0.f) ? __logf(v + 0.5f) : -softplus_f(-v);
}
__device__ __forceinline__ float logaddexp_f(float a, float b) {
    float m = fmaxf(a, b);
    if (m == -INFINITY) return -INFINITY;
    return m + __logf(1.f + __expf(-fabsf(a - b)));
}
// lc = -softplus(k), lsig = -softplus(-k); share log1p(e^-|k|).
__device__ __forceinline__ void lc_lsig(float k, float& lc, float& lsig) {
    float L = __logf(1.f + __expf(-fabsf(k)));
    lc   = -fmaxf(k, 0.f)  - L;
    lsig = -fmaxf(-k, 0.f) - L;
}

// ===========================================================================
// fp16 convert kernel: x (4,194,304 float4) then [Wz;Wh] (524,288 float4)
// ===========================================================================
__global__ void cvt_kernel(const float4* __restrict__ x,
                           const float4* __restrict__ Wz,
                           const float4* __restrict__ Wh)
{
    int i = blockIdx.x * blockDim.x + threadIdx.x;   // < 4718592
    float4 v;
    uint2* dst;
    if (i < 4194304) {
        v = __ldcs(x + i);
        dst = (uint2*)gx + i;
    } else {
        int j = i - 4194304;                          // 0..524287
        v = (j < 262144) ? __ldcs(Wz + j) : __ldcs(Wh + (j - 262144));
        dst = (uint2*)gw + j;
    }
    union { __half h[4]; uint2 u; } o;
    o.h[0] = __float2half_rn(v.x); o.h[1] = __float2half_rn(v.y);
    o.h[2] = __float2half_rn(v.z); o.h[3] = __float2half_rn(v.w);
    *dst = o.u;
}

// ===========================================================================
// fp16 MMA GEMM + fused epilogue (g_lcv + chunk summaries g_A/g_R).
// B-tile row r (0..127): j = r>>5 selects the warp-column's 16-wide h block,
// w = r&31: w<16 -> Wz row (n0*64 + j*16 + w), w>=16 -> Wh row (same h).
// ===========================================================================
__device__ __forceinline__ void load_tile(
    int kt, uint32_t sbase, int m0, int n0, int tid)
{
    int kk = kt << 6;                       // fp16 column offset
    uint32_t bB = sbase + A_BYTES;
#pragma unroll
    for (int i = 0; i < 4; i++) {           // A: 128 rows x 8 chunks
        int idx = i * 256 + tid;
        int r = idx >> 3, c = idx & 7;
        uint32_t dst = sbase + r * 128 + ((c ^ (r & 7)) << 4);
        cp_async16(dst, gx + (((size_t)(m0 + r)) << 10) + kk + (c << 3));
    }
#pragma unroll
    for (int i = 0; i < 4; i++) {           // B: 128 rows x 8 chunks
        int idx = i * 256 + tid;
        int r = idx >> 3, c = idx & 7;
        int j = r >> 5, w = r & 31;
        int grow = (w < 16) ? (n0 * 64 + j * 16 + w)
                            : (1024 + n0 * 64 + j * 16 + (w - 16));
        uint32_t dst = bB + r * 128 + ((c ^ (r & 7)) << 4);
        cp_async16(dst, gw + (((size_t)grow) << 10) + kk + (c << 3));
    }
}

__global__ void __launch_bounds__(256, 2) gemm_mma_kernel(
    const float* __restrict__ bz_g, const float* __restrict__ bh_g)
{
    extern __shared__ __align__(1024) char sm[];
    const uint32_t smem_base = smem_u32(sm);
    const int tid = threadIdx.x;
    const int lane = tid & 31;
    const int wid = tid >> 5;
    const int warp_m = wid >> 2;       // 0..1 : 64-row M half
    const int warp_j = wid & 3;        // 0..3 : 32-row N block (16 h)
    const int n0 = blockIdx.x;         // 0..15
    const int m0 = blockIdx.y * BM;

    // barriers: full[s] = SM_BAR + s*8 (count 256, cp.async completions);
    //           empty[s] = SM_BAR + 24 + s*8 (count 8, warp arrivals)
    if (tid == 0) {
#pragma unroll
        for (int s = 0; s < STAGES; s++) {
            mbar_init(smem_base + SM_BAR + s * 8, 256);
            mbar_init(smem_base + SM_BAR + 24 + s * 8, 8);
        }
    }
    __syncthreads();

    float acc[4][4][4];
#pragma unroll
    for (int a = 0; a < 4; a++)
#pragma unroll
        for (int b = 0; b < 4; b++)
#pragma unroll
            for (int c = 0; c < 4; c++) acc[a][b][c] = 0.f;

    load_tile(0, smem_base + 0 * STAGE_BYTES, m0, n0, tid);
    cp_async_mbar_arrive(smem_base + SM_BAR + 0 * 8);
    load_tile(1, smem_base + 1 * STAGE_BYTES, m0, n0, tid);
    cp_async_mbar_arrive(smem_base + SM_BAR + 1 * 8);

    const int a_row = lane & 15;       // m within 16-tile
    const int a_ch  = lane >> 4;       // k half (chunk select)
    const int b_row = lane & 7;        // n within 8-tile
    const int b_kh  = (lane >> 3) & 1; // k half (chunk select)
    const int b_td  = lane >> 4;       // n8 tile within pair

    for (int kt = 0; kt < NTILES; ++kt) {
        // ---- producer: tile kt+2 into stage (kt+2)%3 ----
        int kp = kt + 2;
        if (kp < NTILES) {
            int sp = kp % STAGES;
            int qp = kp / STAGES;
            if (qp >= 1)               // stage reused: wait compute of kp-3
                mbar_wait(smem_base + SM_BAR + 24 + sp * 8,
                          (uint32_t)((qp - 1) & 1));
            load_tile(kp, smem_base + sp * STAGE_BYTES, m0, n0, tid);
            cp_async_mbar_arrive(smem_base + SM_BAR + sp * 8);
        }

        // ---- consumer: tile kt from stage kt%3 ----
        int s = kt % STAGES;
        mbar_wait(smem_base + SM_BAR + s * 8, (uint32_t)((kt / STAGES) & 1));

        const uint32_t aB = smem_base + s * STAGE_BYTES;
        const uint32_t bB = aB + A_BYTES;
#pragma unroll
        for (int ks = 0; ks < 4; ks++) {   // 4 k16 steps per 64-fp16 tile
            uint32_t af[4][4];
#pragma unroll
            for (int mt = 0; mt < 4; mt++) {
                int r = warp_m * 64 + mt * 16 + a_row;
                int ch = (ks * 2 + a_ch) ^ (r & 7);
                LDSM_X4(af[mt][0], af[mt][1], af[mt][2], af[mt][3],
                        aB + r * 128 + ch * 16);
            }
            uint32_t bf[4][2];
#pragma unroll
            for (int tp = 0; tp < 2; tp++) {
                int r = warp_j * 32 + tp * 16 + b_td * 8 + b_row;
                int ch = (ks * 2 + b_kh) ^ (r & 7);
                LDSM_X4(bf[tp * 2][0], bf[tp * 2][1],
                        bf[tp * 2 + 1][0], bf[tp * 2 + 1][1],
                        bB + r * 128 + ch * 16);
            }
#pragma unroll
            for (int mt = 0; mt < 4; mt++)
#pragma unroll
                for (int t = 0; t < 4; t++)
                    mma_f16(acc[mt][t], af[mt], bf[t]);
        }
        __syncwarp();
        if (lane == 0) mbar_arrive(smem_base + SM_BAR + 24 + s * 8);
    }

    // ---------------- fused epilogue (in-register) ------------------------
    // t = 0..1 hold k, t = 2..3 hold h~ for the same h coordinates.
    // Writes g_lcv AND stores (lc,lv) into the smem transpose tile for the
    // fused chunk-summary pass (pipeline smem is dead now; sync first).
    __syncthreads();                       // all stages consumed; alias smem
    float2* tp = (float2*)sm;              // [128][TP_STRIDE]

    const int gr = lane >> 2;            // 0..7  (row in m16 tile)
    const int gc = (lane & 3) << 1;      // 0,2,4,6 (col pair)
#pragma unroll
    for (int t = 0; t < 2; t++) {
        int hloc = warp_j * 16 + t * 8 + gc;     // local h 0..63
        int h = n0 * 64 + hloc;
        float bz0 = __ldg(bz_g + h),     bz1 = __ldg(bz_g + h + 1);
        float bh0 = __ldg(bh_g + h),     bh1 = __ldg(bh_g + h + 1);
#pragma unroll
        for (int mt = 0; mt < 4; mt++) {
            int rloc = warp_m * 64 + mt * 16 + gr;   // local t row
            int r0 = m0 + rloc;
            const float* ck = acc[mt][t];
            const float* ch = acc[mt][t + 2];
#pragma unroll
            for (int rr = 0; rr < 2; rr++) {
                float k0 = ck[rr * 2 + 0] + bz0;
                float k1 = ck[rr * 2 + 1] + bz1;
                float t0 = ch[rr * 2 + 0] + bh0;
                float t1 = ch[rr * 2 + 1] + bh1;
                float4 o;
                float ls0, ls1;
                lc_lsig(k0, o.x, ls0);
                lc_lsig(k1, o.z, ls1);
                o.y = ls0 + log_g_f(t0);
                o.w = ls1 + log_g_f(t1);
                *(float4*)((float*)g_lcv +
                           (((size_t)(r0 + rr * 8)) * Hc + h) * 2) = o;
                float2* row = tp + (rloc + rr * 8) * TP_STRIDE + hloc;
                row[0] = make_float2(o.x, o.y);
                row[1] = make_float2(o.z, o.w);
            }
        }
    }

    // ---------------- fused chunk summaries -------------------------------
    // 4 chunks x 64 h = 256 threads; each scans 32 sequential t in smem.
    __syncthreads();
    {
        int c  = tid >> 6;                 // 0..3 local chunk
        int hl = tid & 63;                 // local h
        const float2* p = tp + (c * CLEN) * TP_STRIDE + hl;
        float A = 0.f, R = -INFINITY;
#pragma unroll 4
        for (int t = 0; t < CLEN; t++) {
            float2 v = *p; p += TP_STRIDE;
            R = logaddexp_f(R + v.x, v.y);
            A += v.x;
        }
        int bb = m0 >> 12;                               // batch
        int cg = ((m0 & (Tc - 1)) >> 5) + c;             // global chunk
        int idx = cg * BHc + bb * Hc + n0 * 64 + hl;
        g_A[idx] = A;
        g_R[idx] = R;
    }
}

// ===========================================================================
// warp-parallel combine: 1 warp per chain; lane handles chunks 4L..4L+3;
// compose(P then Q) = (P.A + Q.A, logaddexp(P.R + Q.A, Q.R)).
// ===========================================================================
__global__ void scan_combine_kernel(const float* __restrict__ h0)
{
    int gt = blockIdx.x * blockDim.x + threadIdx.x;
    int w = gt >> 5;                   // chain id < 4096
    int lane = gt & 31;
    float lh0 = log_g_f(__ldg(h0 + w));
    int i0 = (lane * 4) * BHc + w;
    float Al[4], Rl[4];
#pragma unroll
    for (int k = 0; k < 4; k++) {
        Al[k] = g_A[i0 + k * BHc];
        Rl[k] = g_R[i0 + k * BHc];
    }
    float Ai = Al[0], Ri = Rl[0];
#pragma unroll
    for (int k = 1; k < 4; k++) {
        Ri = logaddexp_f(Ri + Al[k], Rl[k]);
        Ai = Ai + Al[k];
    }
#pragma unroll
    for (int d = 1; d < 32; d <<= 1) {
        float Au = __shfl_up_sync(0xFFFFFFFFu, Ai, d);
        float Ru = __shfl_up_sync(0xFFFFFFFFu, Ri, d);
        if (lane >= d) {
            Ri = logaddexp_f(Ru + Ai, Ri);
            Ai = Au + Ai;
        }
    }
    float Ae = __shfl_up_sync(0xFFFFFFFFu, Ai, 1);
    float Re = __shfl_up_sync(0xFFFFFFFFu, Ri, 1);
    if (lane == 0) { Ae = 0.f; Re = -INFINITY; }
#pragma unroll
    for (int k = 0; k < 4; k++) {
        g_hin[i0 + k * BHc] = logaddexp_f(Ae + lh0, Re);
        Re = logaddexp_f(Re + Al[k], Rl[k]);
        Ae = Ae + Al[k];
    }
}

// ===========================================================================
// final pass: lh <- logaddexp(lh + lc, lv); out = exp(lh)
// 2 h-adjacent chains per thread (one float4 load per step), 1024 blocks
// for high occupancy; streaming loads/stores (data touched exactly once).
// ===========================================================================
__global__ void scan_final_kernel(float* __restrict__ out)
{
    int g = blockIdx.x * blockDim.x + threadIdx.x;   // < NCHUNK * BHc / 2
    int p = g & (BHc / 2 - 1);
    int c = g >> 11;
    int b = p >> 9;
    int h = (p & 511) << 1;
    size_t base = ((size_t)b * Tc + (size_t)c * CLEN) * Hc + h;
    int idx = c * BHc + b * Hc + h;
    float lh0 = g_hin[idx], lh1 = g_hin[idx + 1];
#pragma unroll 8
    for (int t = 0; t < CLEN; t++) {
        float4 u = __ldcs((const float4*)&g_lcv[base]);
        lh0 = logaddexp_f(lh0 + u.x, u.y);
        lh1 = logaddexp_f(lh1 + u.z, u.w);
        float2 o;
        o.x = __expf(lh0);
        o.y = __expf(lh1);
        __stcs((float2*)&out[base], o);
        base += Hc;
    }
}

// ===========================================================================
extern "C" void kernel_launch(void* const* d_in, const int* in_sizes, int n_in,
                              void* d_out, int out_size)
{
    const float* x  = (const float*)d_in[0];
    const float* h0 = (const float*)d_in[1];
    const float* Wz = (const float*)d_in[2];
    const float* bz = (const float*)d_in[3];
    const float* Wh = (const float*)d_in[4];
    const float* bh = (const float*)d_in[5];
    float* out = (float*)d_out;

    cudaFuncSetAttribute(gemm_mma_kernel,
                         cudaFuncAttributeMaxDynamicSharedMemorySize, SMEM_TOTAL);

    cvt_kernel<<<18432, 256>>>((const float4*)x, (const float4*)Wz,
                               (const float4*)Wh);

    dim3 ggrid(Hc / 64, (Bc * Tc) / BM);   // (16, 128)
    gemm_mma_kernel<<<ggrid, 256, SMEM_TOTAL>>>(bz, bh);

    scan_combine_kernel<<<(BHc * 32) / 256, 256>>>(h0);
    scan_final_kernel<<<(NCHUNK * BHc / 2) / 256, 256>>>(out);
}